// round 7
// baseline (speedup 1.0000x reference)
#include <cuda_runtime.h>

#define GH 768            // grid side
#define OD (GH * 3)       // output side 2304
#define TS 16             // output tile side
#define RR (TS + 2)       // tile + halo
#define NP (RR * RR)      // 324 points
#define NPp (NP + 1)      // padded point stride (odd multiple -> conflict-free chunks)

// Scratch intermediates (device-global arrays: allocation-free scratch).
__device__ float g_h1[GH * GH * 32];
__device__ float g_h2[GH * GH * 32];

__device__ __forceinline__ float dinv_at(int gi, int gj) {
    // deg = (#rows in 3x3 window) * (#cols); self-loop included.
    int rows = (gi > 0) + 1 + (gi < GH - 1);
    int cols = (gj > 0) + 1 + (gj < GH - 1);
    return rsqrtf((float)(rows * cols));
}

__device__ __forceinline__ float4 f4add(float4 a, float4 b) {
    return make_float4(a.x + b.x, a.y + b.y, a.z + b.z, a.w + b.w);
}
__device__ __forceinline__ float4 f4scale(float s, float4 a) {
    return make_float4(s * a.x, s * a.y, s * a.z, s * a.w);
}
__device__ __forceinline__ void f4mac(float4& t, float s, float4 w) {
    t.x += s * w.x; t.y += s * w.y; t.z += s * w.z; t.w += s * w.w;
}

// One GCN layer, stencil-before-matmul form:
//   u = dinv .* h (at load, zero halo), v = boxsum3x3(u)  [CIN channels]
//   out_i = dinv_i * (v_i @ W) + b  [, relu] [, pixel-shuffle store]
template <int CIN, int COUT, bool RELU, bool SHUFFLE>
__global__ void __launch_bounds__(256) gcn_layer(
    const float* __restrict__ in, const float* __restrict__ W,
    const float* __restrict__ b, float* __restrict__ out)
{
    constexpr int CIN4  = (CIN + 3) / 4;
    constexpr int CINp  = CIN4 * 4;        // padded K (zero rows in W_s)
    constexpr int COUT4 = (COUT + 3) / 4;  // padded N/4 (zero cols in W_s)

    extern __shared__ float4 sm4[];
    float4* in_s = sm4;                          // [CIN4][NPp]
    float4* W_s  = sm4 + CIN4 * NPp;             // [CINp][COUT4]
    float4* b_s  = W_s + CINp * COUT4;           // [COUT4]

    const int tid = threadIdx.x;
    const int ntile = GH / TS;
    const int tx = blockIdx.x % ntile;
    const int ty = blockIdx.x / ntile;
    const int gi0 = ty * TS - 1;
    const int gj0 = tx * TS - 1;

    // ---- phase A: zero padded W/bias regions ----
    {
        float* wf = (float*)W_s;
        for (int i = tid; i < (CINp * COUT4 + COUT4) * 4; i += 256) wf[i] = 0.f;
    }
    __syncthreads();

    // ---- phase B: fill W/bias + load tile (scaled by dinv, zero-padded halo) ----
    {
        float* wf = (float*)W_s;
        for (int i = tid; i < CIN * COUT; i += 256) {
            int k = i / COUT, c = i % COUT;
            wf[k * COUT4 * 4 + c] = W[i];
        }
        float* bf = (float*)b_s;
        if (tid < COUT) bf[tid] = b[tid];
    }
    if constexpr (CIN == 3) {
        for (int p = tid; p < NP; p += 256) {
            int pi = p / RR, pj = p % RR;
            int gi = gi0 + pi, gj = gj0 + pj;
            float4 v = make_float4(0.f, 0.f, 0.f, 0.f);
            if ((unsigned)gi < GH && (unsigned)gj < GH) {
                const float* src = &in[(gi * GH + gj) * 3];
                float d = dinv_at(gi, gj);
                v = make_float4(d * src[0], d * src[1], d * src[2], 0.f);
            }
            in_s[p] = v;
        }
    } else {
        static_assert(CIN == 3 || (CIN % 4) == 0, "CIN vectorization");
        for (int idx = tid; idx < NP * CIN4; idx += 256) {
            int p = idx / CIN4, c4 = idx % CIN4;
            int pi = p / RR, pj = p % RR;
            int gi = gi0 + pi, gj = gj0 + pj;
            float4 v = make_float4(0.f, 0.f, 0.f, 0.f);
            if ((unsigned)gi < GH && (unsigned)gj < GH) {
                v = *reinterpret_cast<const float4*>(
                        &in[(gi * GH + gj) * CIN + 4 * c4]);
                v = f4scale(dinv_at(gi, gj), v);
            }
            in_s[c4 * NPp + p] = v;
        }
    }
    __syncthreads();

    // ---- phase C: per-pixel 3x3 box-sum (CIN channels) ----
    const int pi = tid >> 4, pj = tid & 15;
    const int pc = (pi + 1) * RR + (pj + 1);

    float4 vs[CIN4];
#pragma unroll
    for (int c4 = 0; c4 < CIN4; ++c4) {
        const float4* sp = in_s + c4 * NPp + pc;
        float4 a = f4add(f4add(sp[-RR - 1], sp[-RR]), sp[-RR + 1]);
        float4 m = f4add(f4add(sp[-1],      sp[0]),   sp[1]);
        float4 d = f4add(f4add(sp[RR - 1],  sp[RR]),  sp[RR + 1]);
        vs[c4] = f4add(f4add(a, m), d);
    }

    // ---- phase D: matmul v @ W (W rows broadcast from smem) ----
    float4 t[COUT4];
#pragma unroll
    for (int c4 = 0; c4 < COUT4; ++c4) t[c4] = make_float4(0.f, 0.f, 0.f, 0.f);
#pragma unroll
    for (int k4 = 0; k4 < CIN4; ++k4) {
        const float4 v = vs[k4];
        const float4* w0 = W_s + (4 * k4 + 0) * COUT4;
        const float4* w1 = W_s + (4 * k4 + 1) * COUT4;
        const float4* w2 = W_s + (4 * k4 + 2) * COUT4;
        const float4* w3 = W_s + (4 * k4 + 3) * COUT4;
#pragma unroll
        for (int c4 = 0; c4 < COUT4; ++c4) {
            f4mac(t[c4], v.x, w0[c4]);
            f4mac(t[c4], v.y, w1[c4]);
            f4mac(t[c4], v.z, w2[c4]);
            f4mac(t[c4], v.w, w3[c4]);
        }
    }

    // ---- phase E: scale + bias (+relu) ----
    const int gi = gi0 + pi + 1, gj = gj0 + pj + 1;
    const float dc = dinv_at(gi, gj);
#pragma unroll
    for (int c4 = 0; c4 < COUT4; ++c4) {
        float4 bb = b_s[c4];
        t[c4].x = dc * t[c4].x + bb.x;
        t[c4].y = dc * t[c4].y + bb.y;
        t[c4].z = dc * t[c4].z + bb.z;
        t[c4].w = dc * t[c4].w + bb.w;
        if constexpr (RELU) {
            t[c4].x = fmaxf(t[c4].x, 0.f); t[c4].y = fmaxf(t[c4].y, 0.f);
            t[c4].z = fmaxf(t[c4].z, 0.f); t[c4].w = fmaxf(t[c4].w, 0.f);
        }
    }

    // ---- phase F: store ----
    if constexpr (!SHUFFLE) {
        static_assert(SHUFFLE || (COUT % 4) == 0, "vector store");
        float4* o4 = reinterpret_cast<float4*>(&out[(gi * GH + gj) * COUT]);
#pragma unroll
        for (int c4 = 0; c4 < COUT4; ++c4) o4[c4] = t[c4];
    } else {
        // pixel-shuffle (S=3): stage 48x48 tile in smem, then coalesced stores.
        __syncthreads();                       // all stencil reads done
        float* stage = (float*)sm4;            // [48][48]
        const int r0 = pi * 3, q0 = pj * 3;
        stage[(r0 + 0) * 48 + q0 + 0] = t[0].x;
        stage[(r0 + 0) * 48 + q0 + 1] = t[0].y;
        stage[(r0 + 0) * 48 + q0 + 2] = t[0].z;
        stage[(r0 + 1) * 48 + q0 + 0] = t[0].w;
        stage[(r0 + 1) * 48 + q0 + 1] = t[1].x;
        stage[(r0 + 1) * 48 + q0 + 2] = t[1].y;
        stage[(r0 + 2) * 48 + q0 + 0] = t[1].z;
        stage[(r0 + 2) * 48 + q0 + 1] = t[1].w;
        stage[(r0 + 2) * 48 + q0 + 2] = t[2].x;
        __syncthreads();
        const int orow0 = ty * 48, ocol0 = tx * 48;
        for (int idx = tid; idx < 48 * 12; idx += 256) {
            int r = idx / 12, v = idx % 12;
            float4 val = *reinterpret_cast<const float4*>(&stage[r * 48 + v * 4]);
            *reinterpret_cast<float4*>(&out[(orow0 + r) * OD + ocol0 + v * 4]) = val;
        }
    }
}

static inline int smem_bytes(int cin, int cout) {
    int cin4 = (cin + 3) / 4, cout4 = (cout + 3) / 4;
    return (cin4 * NPp + cin4 * 4 * cout4 + cout4) * 16;
}

extern "C" void kernel_launch(void* const* d_in, const int* in_sizes, int n_in,
                              void* d_out, int out_size) {
    const float* x  = (const float*)d_in[0];
    // d_in[1] = edge_index (int32) — grid structure known analytically; unused.
    const float* W1 = (const float*)d_in[2];
    const float* b1 = (const float*)d_in[3];
    const float* W2 = (const float*)d_in[4];
    const float* b2 = (const float*)d_in[5];
    const float* W3 = (const float*)d_in[6];
    const float* b3 = (const float*)d_in[7];
    float* out = (float*)d_out;

    float *h1, *h2;
    cudaGetSymbolAddress((void**)&h1, g_h1);
    cudaGetSymbolAddress((void**)&h2, g_h2);

    const int ntile = GH / TS;
    const dim3 grid(ntile * ntile);
    const dim3 block(256);

    int s1 = smem_bytes(3, 32);
    int s2 = smem_bytes(32, 32);
    int s3 = smem_bytes(32, 9);
    cudaFuncSetAttribute(gcn_layer<3, 32, true, false>,
                         cudaFuncAttributeMaxDynamicSharedMemorySize, s1);
    cudaFuncSetAttribute(gcn_layer<32, 32, true, false>,
                         cudaFuncAttributeMaxDynamicSharedMemorySize, s2);
    cudaFuncSetAttribute(gcn_layer<32, 9, false, true>,
                         cudaFuncAttributeMaxDynamicSharedMemorySize, s3);

    gcn_layer<3, 32, true, false><<<grid, block, s1>>>(x,  W1, b1, h1);
    gcn_layer<32, 32, true, false><<<grid, block, s2>>>(h1, W2, b2, h2);
    gcn_layer<32, 9, false, true><<<grid, block, s3>>>(h2, W3, b3, out);
}

// round 14
// speedup vs baseline: 1.0473x; 1.0473x over previous
#include <cuda_runtime.h>

#define GH 768            // grid side
#define OD (GH * 3)       // output side 2304
#define TS 16             // output tile side
#define RR (TS + 2)       // tile + halo
#define NP (RR * RR)      // 324 points
#define NPp (NP + 1)      // padded point stride (odd -> conflict-free chunks)

// Scratch intermediates (device-global arrays: allocation-free scratch).
__device__ float g_h1[GH * GH * 32];
__device__ float g_h2[GH * GH * 32];

typedef unsigned long long u64;

__device__ __forceinline__ float dinv_at(int gi, int gj) {
    int rows = (gi > 0) + 1 + (gi < GH - 1);
    int cols = (gj > 0) + 1 + (gj < GH - 1);
    return rsqrtf((float)(rows * cols));
}

__device__ __forceinline__ float4 f4scale(float s, float4 a) {
    return make_float4(s * a.x, s * a.y, s * a.z, s * a.w);
}

// ---- packed f32x2 ops (sm_103a; FFMA2 is PTX-only) ----
__device__ __forceinline__ u64 pack2(float a, float b) {
    u64 r;
    asm("mov.b64 %0, {%1, %2};" : "=l"(r) : "f"(a), "f"(b));
    return r;
}
__device__ __forceinline__ void unpack2(u64 v, float& a, float& b) {
    asm("mov.b64 {%0, %1}, %2;" : "=f"(a), "=f"(b) : "l"(v));
}
__device__ __forceinline__ u64 add2(u64 a, u64 b) {
    u64 d;
    asm("add.rn.f32x2 %0, %1, %2;" : "=l"(d) : "l"(a), "l"(b));
    return d;
}
__device__ __forceinline__ u64 fma2(u64 a, u64 b, u64 c) {
    u64 d;
    asm("fma.rn.f32x2 %0, %1, %2, %3;" : "=l"(d) : "l"(a), "l"(b), "l"(c));
    return d;
}

// One GCN layer, stencil-before-matmul form, stencil fused into the K-loop:
//   u = dinv .* h (at load, zero halo)
//   per channel-group k4: v4 = boxsum3x3(u[k4]); t += v4 (x) W[4k4..4k4+3]
//   out_i = dinv_i * t + b  [, relu] [, pixel-shuffle store]
template <int CIN, int COUT, bool RELU, bool SHUFFLE>
__global__ void __launch_bounds__(256, 4) gcn_layer(
    const float* __restrict__ in, const float* __restrict__ W,
    const float* __restrict__ b, float* __restrict__ out)
{
    constexpr int CIN4  = (CIN + 3) / 4;
    constexpr int CINp  = CIN4 * 4;        // padded K (zero rows in W_s)
    constexpr int COUT4 = (COUT + 3) / 4;  // padded N/4 (zero cols in W_s)
    constexpr int COUT2 = COUT4 * 2;       // accumulators as f32x2 pairs

    extern __shared__ float4 sm4[];
    float4* in_s = sm4;                          // [CIN4][NPp]
    float4* W_s  = sm4 + CIN4 * NPp;             // [CINp][COUT4]
    float4* b_s  = W_s + CINp * COUT4;           // [COUT4]

    const int tid = threadIdx.x;
    const int ntile = GH / TS;
    const int tx = blockIdx.x % ntile;
    const int ty = blockIdx.x / ntile;
    const int gi0 = ty * TS - 1;
    const int gj0 = tx * TS - 1;

    // ---- phase A: zero padded W/bias regions ----
    {
        float* wf = (float*)W_s;
        for (int i = tid; i < (CINp * COUT4 + COUT4) * 4; i += 256) wf[i] = 0.f;
    }
    __syncthreads();

    // ---- phase B: fill W/bias + load tile (scaled by dinv, zero-padded halo) ----
    {
        float* wf = (float*)W_s;
        for (int i = tid; i < CIN * COUT; i += 256) {
            int k = i / COUT, c = i % COUT;
            wf[k * COUT4 * 4 + c] = W[i];
        }
        float* bf = (float*)b_s;
        if (tid < COUT) bf[tid] = b[tid];
    }
    if constexpr (CIN == 3) {
        for (int p = tid; p < NP; p += 256) {
            int pi = p / RR, pj = p % RR;
            int gi = gi0 + pi, gj = gj0 + pj;
            float4 v = make_float4(0.f, 0.f, 0.f, 0.f);
            if ((unsigned)gi < GH && (unsigned)gj < GH) {
                const float* src = &in[(gi * GH + gj) * 3];
                float d = dinv_at(gi, gj);
                v = make_float4(d * src[0], d * src[1], d * src[2], 0.f);
            }
            in_s[p] = v;
        }
    } else {
        static_assert(CIN == 3 || (CIN % 4) == 0, "CIN vectorization");
        for (int idx = tid; idx < NP * CIN4; idx += 256) {
            int p = idx / CIN4, c4 = idx % CIN4;
            int pi = p / RR, pj = p % RR;
            int gi = gi0 + pi, gj = gj0 + pj;
            float4 v = make_float4(0.f, 0.f, 0.f, 0.f);
            if ((unsigned)gi < GH && (unsigned)gj < GH) {
                v = *reinterpret_cast<const float4*>(
                        &in[(gi * GH + gj) * CIN + 4 * c4]);
                v = f4scale(dinv_at(gi, gj), v);
            }
            in_s[c4 * NPp + p] = v;
        }
    }
    __syncthreads();

    // ---- phase C+D fused: per k4, 3x3 box-sum then rank-4 update of t ----
    const int pi = tid >> 4, pj = tid & 15;
    const int pc = (pi + 1) * RR + (pj + 1);

    u64 t2[COUT2];
#pragma unroll
    for (int c2 = 0; c2 < COUT2; ++c2) t2[c2] = 0ull;

    const u64* Wu = reinterpret_cast<const u64*>(W_s);  // rows of COUT2 pairs

#pragma unroll
    for (int k4 = 0; k4 < CIN4; ++k4) {
        // 9-tap box sum on channel group k4 (packed halves)
        const ulonglong2* sp =
            reinterpret_cast<const ulonglong2*>(in_s + k4 * NPp + pc);
        ulonglong2 s;
        u64 lo, hi;
        s = sp[-RR - 1]; lo = s.x;            hi = s.y;
        s = sp[-RR];     lo = add2(lo, s.x);  hi = add2(hi, s.y);
        s = sp[-RR + 1]; lo = add2(lo, s.x);  hi = add2(hi, s.y);
        s = sp[-1];      lo = add2(lo, s.x);  hi = add2(hi, s.y);
        s = sp[0];       lo = add2(lo, s.x);  hi = add2(hi, s.y);
        s = sp[1];       lo = add2(lo, s.x);  hi = add2(hi, s.y);
        s = sp[RR - 1];  lo = add2(lo, s.x);  hi = add2(hi, s.y);
        s = sp[RR];      lo = add2(lo, s.x);  hi = add2(hi, s.y);
        s = sp[RR + 1];  lo = add2(lo, s.x);  hi = add2(hi, s.y);

        float a0, a1, a2, a3;
        unpack2(lo, a0, a1);
        unpack2(hi, a2, a3);
        const u64 p0 = pack2(a0, a0), p1 = pack2(a1, a1);
        const u64 p2 = pack2(a2, a2), p3 = pack2(a3, a3);

        const u64* w0 = Wu + (4 * k4 + 0) * COUT2;
        const u64* w1 = Wu + (4 * k4 + 1) * COUT2;
        const u64* w2 = Wu + (4 * k4 + 2) * COUT2;
        const u64* w3 = Wu + (4 * k4 + 3) * COUT2;
#pragma unroll
        for (int c2 = 0; c2 < COUT2; ++c2) t2[c2] = fma2(p0, w0[c2], t2[c2]);
#pragma unroll
        for (int c2 = 0; c2 < COUT2; ++c2) t2[c2] = fma2(p1, w1[c2], t2[c2]);
#pragma unroll
        for (int c2 = 0; c2 < COUT2; ++c2) t2[c2] = fma2(p2, w2[c2], t2[c2]);
#pragma unroll
        for (int c2 = 0; c2 < COUT2; ++c2) t2[c2] = fma2(p3, w3[c2], t2[c2]);
    }

    // ---- phase E: scale + bias (+relu) ----
    const int gi = gi0 + pi + 1, gj = gj0 + pj + 1;
    const float dc = dinv_at(gi, gj);
    float o[COUT4 * 4];
    {
        const float* bf = (const float*)b_s;
#pragma unroll
        for (int c2 = 0; c2 < COUT2; ++c2) {
            float v0, v1;
            unpack2(t2[c2], v0, v1);
            v0 = dc * v0 + bf[2 * c2 + 0];
            v1 = dc * v1 + bf[2 * c2 + 1];
            if constexpr (RELU) { v0 = fmaxf(v0, 0.f); v1 = fmaxf(v1, 0.f); }
            o[2 * c2 + 0] = v0;
            o[2 * c2 + 1] = v1;
        }
    }

    // ---- phase F: store ----
    if constexpr (!SHUFFLE) {
        static_assert(SHUFFLE || (COUT % 4) == 0, "vector store");
        float4* o4 = reinterpret_cast<float4*>(&out[(gi * GH + gj) * COUT]);
#pragma unroll
        for (int c4 = 0; c4 < COUT4; ++c4)
            o4[c4] = make_float4(o[4 * c4], o[4 * c4 + 1],
                                 o[4 * c4 + 2], o[4 * c4 + 3]);
    } else {
        // pixel-shuffle (S=3): stage 48x48 tile in smem, then coalesced stores.
        __syncthreads();                       // all stencil reads done
        float* stage = (float*)sm4;            // [48][48]
        const int r0 = pi * 3, q0 = pj * 3;
#pragma unroll
        for (int c = 0; c < 9; ++c)
            stage[(r0 + c / 3) * 48 + q0 + c % 3] = o[c];
        __syncthreads();
        const int orow0 = ty * 48, ocol0 = tx * 48;
        for (int idx = tid; idx < 48 * 12; idx += 256) {
            int r = idx / 12, v = idx % 12;
            float4 val = *reinterpret_cast<const float4*>(&stage[r * 48 + v * 4]);
            *reinterpret_cast<float4*>(&out[(orow0 + r) * OD + ocol0 + v * 4]) = val;
        }
    }
}

static inline int smem_bytes(int cin, int cout) {
    int cin4 = (cin + 3) / 4, cout4 = (cout + 3) / 4;
    return (cin4 * NPp + cin4 * 4 * cout4 + cout4) * 16;
}

extern "C" void kernel_launch(void* const* d_in, const int* in_sizes, int n_in,
                              void* d_out, int out_size) {
    const float* x  = (const float*)d_in[0];
    // d_in[1] = edge_index (int32) — grid structure known analytically; unused.
    const float* W1 = (const float*)d_in[2];
    const float* b1 = (const float*)d_in[3];
    const float* W2 = (const float*)d_in[4];
    const float* b2 = (const float*)d_in[5];
    const float* W3 = (const float*)d_in[6];
    const float* b3 = (const float*)d_in[7];
    float* out = (float*)d_out;

    float *h1, *h2;
    cudaGetSymbolAddress((void**)&h1, g_h1);
    cudaGetSymbolAddress((void**)&h2, g_h2);

    const int ntile = GH / TS;
    const dim3 grid(ntile * ntile);
    const dim3 block(256);

    int s1 = smem_bytes(3, 32);
    int s2 = smem_bytes(32, 32);
    int s3 = smem_bytes(32, 9);
    cudaFuncSetAttribute(gcn_layer<3, 32, true, false>,
                         cudaFuncAttributeMaxDynamicSharedMemorySize, s1);
    cudaFuncSetAttribute(gcn_layer<32, 32, true, false>,
                         cudaFuncAttributeMaxDynamicSharedMemorySize, s2);
    cudaFuncSetAttribute(gcn_layer<32, 9, false, true>,
                         cudaFuncAttributeMaxDynamicSharedMemorySize, s3);

    gcn_layer<3, 32, true, false><<<grid, block, s1>>>(x,  W1, b1, h1);
    gcn_layer<32, 32, true, false><<<grid, block, s2>>>(h1, W2, b2, h2);
    gcn_layer<32, 9, false, true><<<grid, block, s3>>>(h2, W3, b3, out);
}